// round 1
// baseline (speedup 1.0000x reference)
#include <cuda_runtime.h>
#include <math.h>

// ---------------- problem constants (static in reference) ----------------
#define NB 4
#define LQ 13294
#define LEN_IN 13294
#define CC 256
#define MH 8          // heads
#define LV 4          // levels
#define PT 4          // points
#define DH 32         // head dim
#define NROWS (NB * LQ)   // 53176

__device__ __constant__ int c_H[LV]     = {100, 50, 25, 13};
__device__ __constant__ int c_W[LV]     = {100, 50, 25, 13};
__device__ __constant__ int c_start[LV] = {0, 10000, 12500, 13125};

// ---------------- scratch (device globals, no allocation) ----------------
__device__ float g_value[NROWS * CC];   // (n, len, M*D) value projection
__device__ float g_off[NROWS * CC];     // (n, lq, M*L*P*2) offset logits
__device__ float g_attn[NROWS * 128];   // (n, lq, M*L*P) attn logits
__device__ float g_ms[NROWS * CC];      // (n, lq, C) sampled output

// ---------------- SGEMM: C = A(MxK) @ B(KxN) + bias, K=256 ----------------
#define BM 64
#define BN 64
#define BK 16

__global__ __launch_bounds__(256) void sgemm_bias(
    const float* __restrict__ A, const float* __restrict__ B,
    const float* __restrict__ bias, float* __restrict__ Cmat,
    int Mrows, int Ncols)
{
    __shared__ float As[BK][BM + 4];
    __shared__ float Bs[BK][BN];

    const int tid = threadIdx.x;
    const int tx = tid & 15;        // 0..15 -> N direction
    const int ty = tid >> 4;        // 0..15 -> M direction
    const int row0 = blockIdx.y * BM;
    const int col0 = blockIdx.x * BN;
    const int K = CC;

    // A tile load mapping: 64 rows x 16 k, one float4 per thread
    const int arow = tid >> 2;           // 0..63
    const int aseg = (tid & 3) << 2;     // 0,4,8,12
    // B tile load mapping: 16 k x 64 cols, one float4 per thread
    const int brow = tid >> 4;           // 0..15
    const int bseg = (tid & 15) << 2;    // 0..60

    float acc[4][4] = {};

    for (int k0 = 0; k0 < K; k0 += BK) {
        float4 av = make_float4(0.f, 0.f, 0.f, 0.f);
        int gr = row0 + arow;
        if (gr < Mrows)
            av = *reinterpret_cast<const float4*>(A + (size_t)gr * K + k0 + aseg);
        As[aseg + 0][arow] = av.x;
        As[aseg + 1][arow] = av.y;
        As[aseg + 2][arow] = av.z;
        As[aseg + 3][arow] = av.w;

        float4 bv = *reinterpret_cast<const float4*>(
            B + (size_t)(k0 + brow) * Ncols + col0 + bseg);
        *reinterpret_cast<float4*>(&Bs[brow][bseg]) = bv;

        __syncthreads();

        #pragma unroll
        for (int k = 0; k < BK; k++) {
            float a[4], b[4];
            #pragma unroll
            for (int i = 0; i < 4; i++) a[i] = As[k][ty * 4 + i];
            #pragma unroll
            for (int j = 0; j < 4; j++) b[j] = Bs[k][tx * 4 + j];
            #pragma unroll
            for (int i = 0; i < 4; i++)
                #pragma unroll
                for (int j = 0; j < 4; j++)
                    acc[i][j] = fmaf(a[i], b[j], acc[i][j]);
        }
        __syncthreads();
    }

    #pragma unroll
    for (int i = 0; i < 4; i++) {
        int gr = row0 + ty * 4 + i;
        if (gr >= Mrows) continue;
        #pragma unroll
        for (int j = 0; j < 4; j++) {
            int gc = col0 + tx * 4 + j;
            Cmat[(size_t)gr * Ncols + gc] = acc[i][j] + bias[gc];
        }
    }
}

// ---------------- sampling: one warp per (n, q, m) ----------------
__global__ __launch_bounds__(256) void msda_sample(const float* __restrict__ refpts)
{
    const int nq = blockIdx.x;           // 0..NROWS-1 == n*LQ + q
    const int m = threadIdx.x >> 5;      // head 0..7
    const int lane = threadIdx.x & 31;
    const int n = nq / LQ;

    // reference points (L*2 = 8 floats), broadcast via shuffle
    float refv = 0.f;
    if (lane < 8) refv = refpts[(size_t)nq * 8 + lane];

    // offset logits for this head: 32 floats = 16 points x (x,y)
    float offv = g_off[(size_t)nq * 256 + m * 32 + lane];

    // attention logits: 16 values, softmax within lanes 0..15
    float logit = (lane < 16) ? g_attn[(size_t)nq * 128 + m * 16 + lane] : -1e30f;
    float mx = logit;
    #pragma unroll
    for (int o = 8; o >= 1; o >>= 1)
        mx = fmaxf(mx, __shfl_xor_sync(0xffffffffu, mx, o, 16));
    float e = __expf(logit - mx);
    float s = e;
    #pragma unroll
    for (int o = 8; o >= 1; o >>= 1)
        s += __shfl_xor_sync(0xffffffffu, s, o, 16);
    float prob = e / s;

    const float* vbase = g_value + (size_t)n * LEN_IN * CC;
    float acc = 0.f;

    #pragma unroll 4
    for (int p = 0; p < 16; p++) {
        const int l = p >> 2;
        float w  = __shfl_sync(0xffffffffu, prob, p);
        float ox = __shfl_sync(0xffffffffu, offv, 2 * p);
        float oy = __shfl_sync(0xffffffffu, offv, 2 * p + 1);
        float rx = __shfl_sync(0xffffffffu, refv, 2 * l);
        float ry = __shfl_sync(0xffffffffu, refv, 2 * l + 1);

        const int Wi = c_W[l], Hi = c_H[l];
        const float Wf = (float)Wi, Hf = (float)Hi;
        float lx = rx + ox / Wf;
        float ly = ry + oy / Hf;
        float x = lx * Wf - 0.5f;
        float y = ly * Hf - 0.5f;
        float x0f = floorf(x), y0f = floorf(y);
        float wx = x - x0f, wy = y - y0f;
        int x0 = (int)x0f, y0 = (int)y0f;
        const int rowbase = c_start[l];

        #pragma unroll
        for (int cidx = 0; cidx < 4; cidx++) {
            int dx = cidx & 1, dy = cidx >> 1;
            int xi = x0 + dx, yi = y0 + dy;
            float cw = (dx ? wx : 1.f - wx) * (dy ? wy : 1.f - wy);
            if (xi >= 0 && xi < Wi && yi >= 0 && yi < Hi) {
                const float* vp = vbase +
                    (size_t)(rowbase + yi * Wi + xi) * CC + m * 32 + lane;
                acc = fmaf(__ldg(vp), cw * w, acc);
            }
        }
    }

    g_ms[(size_t)nq * 256 + m * 32 + lane] = acc;
}

// ---------------- launch ----------------
extern "C" void kernel_launch(void* const* d_in, const int* in_sizes, int n_in,
                              void* d_out, int out_size)
{
    const float* query         = (const float*)d_in[0];
    const float* refpts        = (const float*)d_in[1];
    const float* input_flatten = (const float*)d_in[2];
    // d_in[3] = input_space_shape, d_in[4] = input_level_start_idx (hardcoded)
    const float* Wv     = (const float*)d_in[5];
    const float* bv     = (const float*)d_in[6];
    const float* W_off  = (const float*)d_in[7];
    const float* b_off  = (const float*)d_in[8];
    const float* W_attn = (const float*)d_in[9];
    const float* b_attn = (const float*)d_in[10];
    const float* Wo     = (const float*)d_in[11];
    const float* bo     = (const float*)d_in[12];
    float* out = (float*)d_out;

    float *p_value, *p_off, *p_attn, *p_ms;
    cudaGetSymbolAddress((void**)&p_value, g_value);
    cudaGetSymbolAddress((void**)&p_off,   g_off);
    cudaGetSymbolAddress((void**)&p_attn,  g_attn);
    cudaGetSymbolAddress((void**)&p_ms,    g_ms);

    dim3 blk(256);
    dim3 g256(256 / BN, (NROWS + BM - 1) / BM);   // (4, 831)
    dim3 g128(128 / BN, (NROWS + BM - 1) / BM);   // (2, 831)

    // 1. value projection
    sgemm_bias<<<g256, blk>>>(input_flatten, Wv, bv, p_value, NROWS, 256);
    // 2. sampling offset logits
    sgemm_bias<<<g256, blk>>>(query, W_off, b_off, p_off, NROWS, 256);
    // 3. attention logits
    sgemm_bias<<<g128, blk>>>(query, W_attn, b_attn, p_attn, NROWS, 128);
    // 4. deformable sampling
    msda_sample<<<NROWS, 256>>>(refpts);
    // 5. output projection
    sgemm_bias<<<g256, blk>>>(p_ms, Wo, bo, out, NROWS, 256);
}

// round 2
// speedup vs baseline: 2.3735x; 2.3735x over previous
#include <cuda_runtime.h>
#include <math.h>
#include <stdint.h>

// ---------------- problem constants (static in reference) ----------------
#define NB 4
#define LQ 13294
#define LEN_IN 13294
#define CC 256
#define NROWS (NB * LQ)   // 53176

__device__ __constant__ int c_H[4]     = {100, 50, 25, 13};
__device__ __constant__ int c_W[4]     = {100, 50, 25, 13};
__device__ __constant__ int c_start[4] = {0, 10000, 12500, 13125};

// ---------------- scratch (device globals, no allocation) ----------------
__device__ float g_value[NROWS * CC];   // (n, len, M*D) value projection
__device__ float g_off[NROWS * CC];     // (n, lq, M*L*P*2) offset logits
__device__ float g_attn[NROWS * 128];   // (n, lq, M*L*P) attn logits
__device__ float g_ms[NROWS * CC];      // (n, lq, C) sampled output

// ---------------- tf32 tensor-core GEMM ----------------
// C(Mrows x Ncols) = A(Mrows x 256) @ B(256 x Ncols) + bias
// block tile 128x128x32, 8 warps (4 in M x 2 in N), warp tile 32x64
#define BM 128
#define BN 128
#define BK 32
#define ASTRIDE 36    // [m][k] k-stride padded: frag banks = (4m + c) % 32, conflict-free
#define BSTRIDE 136   // [k][n] n-stride padded: frag banks = (8c + r) % 32, conflict-free

__device__ __forceinline__ uint32_t f2tf32(float x) {
    uint32_t r;
    asm("cvt.rna.tf32.f32 %0, %1;" : "=r"(r) : "f"(x));
    return r;
}

__device__ __forceinline__ void mma_tf32(float* d, const uint32_t* a,
                                         uint32_t b0, uint32_t b1) {
    asm volatile(
        "mma.sync.aligned.m16n8k8.row.col.f32.tf32.tf32.f32 "
        "{%0,%1,%2,%3},{%4,%5,%6,%7},{%8,%9},{%0,%1,%2,%3};"
        : "+f"(d[0]), "+f"(d[1]), "+f"(d[2]), "+f"(d[3])
        : "r"(a[0]), "r"(a[1]), "r"(a[2]), "r"(a[3]), "r"(b0), "r"(b1));
}

__global__ __launch_bounds__(256, 2) void gemm_tf32_bias(
    const float* __restrict__ A, const float* __restrict__ B,
    const float* __restrict__ bias, float* __restrict__ Cmat,
    int Mrows, int Ncols)
{
    __shared__ uint32_t As[BM][ASTRIDE];   // [m][k] tf32
    __shared__ uint32_t Bs[BK][BSTRIDE];   // [k][n] tf32

    const int tid  = threadIdx.x;
    const int lane = tid & 31;
    const int wid  = tid >> 5;
    const int wm   = (wid & 3) * 32;   // warp M offset in tile
    const int wn   = (wid >> 2) * 64;  // warp N offset in tile
    const int row0 = blockIdx.y * BM;
    const int col0 = blockIdx.x * BN;
    const int K = CC;

    const int r  = lane >> 2;        // 0..7
    const int c  = lane & 3;         // 0..3

    float acc[2][8][4];
    #pragma unroll
    for (int mt = 0; mt < 2; mt++)
        #pragma unroll
        for (int nt = 0; nt < 8; nt++)
            #pragma unroll
            for (int i = 0; i < 4; i++) acc[mt][nt][i] = 0.f;

    for (int k0 = 0; k0 < K; k0 += BK) {
        // ---- load A tile (128 x 32) -> As[m][k], tf32-convert ----
        #pragma unroll
        for (int j = 0; j < 4; j++) {
            int idx = tid + 256 * j;          // 0..1023
            int m = idx >> 3;                 // 0..127
            int kseg = (idx & 7) << 2;        // 0,4,...,28
            int gr = row0 + m;
            float4 v = make_float4(0.f, 0.f, 0.f, 0.f);
            if (gr < Mrows)
                v = *reinterpret_cast<const float4*>(A + (size_t)gr * K + k0 + kseg);
            uint4 u;
            u.x = f2tf32(v.x); u.y = f2tf32(v.y);
            u.z = f2tf32(v.z); u.w = f2tf32(v.w);
            *reinterpret_cast<uint4*>(&As[m][kseg]) = u;
        }
        // ---- load B tile (32 x 128) -> Bs[k][n], tf32-convert ----
        #pragma unroll
        for (int j = 0; j < 4; j++) {
            int idx = tid + 256 * j;          // 0..1023
            int k = idx >> 5;                 // 0..31
            int seg = (idx & 31) << 2;        // 0..124
            float4 v = *reinterpret_cast<const float4*>(
                B + (size_t)(k0 + k) * Ncols + col0 + seg);
            uint4 u;
            u.x = f2tf32(v.x); u.y = f2tf32(v.y);
            u.z = f2tf32(v.z); u.w = f2tf32(v.w);
            *reinterpret_cast<uint4*>(&Bs[k][seg]) = u;
        }
        __syncthreads();

        // ---- 4 k-slices of 8 ----
        #pragma unroll
        for (int ks = 0; ks < 4; ks++) {
            const int kk = ks * 8;
            uint32_t afr[2][4];
            #pragma unroll
            for (int mt = 0; mt < 2; mt++) {
                int mbase = wm + mt * 16 + r;
                afr[mt][0] = As[mbase][kk + c];
                afr[mt][1] = As[mbase + 8][kk + c];
                afr[mt][2] = As[mbase][kk + c + 4];
                afr[mt][3] = As[mbase + 8][kk + c + 4];
            }
            #pragma unroll
            for (int nt = 0; nt < 8; nt++) {
                int nbase = wn + nt * 8 + r;
                uint32_t b0 = Bs[kk + c][nbase];
                uint32_t b1 = Bs[kk + c + 4][nbase];
                mma_tf32(acc[0][nt], afr[0], b0, b1);
                mma_tf32(acc[1][nt], afr[1], b0, b1);
            }
        }
        __syncthreads();
    }

    // ---- epilogue: + bias, guarded stores ----
    const int c2 = c * 2;
    #pragma unroll
    for (int mt = 0; mt < 2; mt++) {
        int row = row0 + wm + mt * 16 + r;
        #pragma unroll
        for (int nt = 0; nt < 8; nt++) {
            int col = col0 + wn + nt * 8 + c2;
            float b0 = __ldg(bias + col);
            float b1 = __ldg(bias + col + 1);
            if (row < Mrows) {
                float2 v = make_float2(acc[mt][nt][0] + b0, acc[mt][nt][1] + b1);
                *reinterpret_cast<float2*>(Cmat + (size_t)row * Ncols + col) = v;
            }
            if (row + 8 < Mrows) {
                float2 v = make_float2(acc[mt][nt][2] + b0, acc[mt][nt][3] + b1);
                *reinterpret_cast<float2*>(Cmat + (size_t)(row + 8) * Ncols + col) = v;
            }
        }
    }
}

// ---------------- sampling: one warp per (n, q, m-pair) ----------------
__global__ __launch_bounds__(256) void msda_sample(const float* __restrict__ refpts)
{
    const int nq = blockIdx.x;           // 0..NROWS-1 == n*LQ + q
    const int m = threadIdx.x >> 5;      // head 0..7
    const int lane = threadIdx.x & 31;
    const int n = nq / LQ;

    // reference points (L*2 = 8 floats), broadcast via shuffle
    float refv = 0.f;
    if (lane < 8) refv = refpts[(size_t)nq * 8 + lane];

    // offset logits for this head: 32 floats = 16 points x (x,y)
    float offv = g_off[(size_t)nq * 256 + m * 32 + lane];

    // attention logits: 16 values, softmax within lanes 0..15
    float logit = (lane < 16) ? g_attn[(size_t)nq * 128 + m * 16 + lane] : -1e30f;
    float mx = logit;
    #pragma unroll
    for (int o = 8; o >= 1; o >>= 1)
        mx = fmaxf(mx, __shfl_xor_sync(0xffffffffu, mx, o, 16));
    float e = __expf(logit - mx);
    float s = e;
    #pragma unroll
    for (int o = 8; o >= 1; o >>= 1)
        s += __shfl_xor_sync(0xffffffffu, s, o, 16);
    float prob = e / s;

    const float* vbase = g_value + (size_t)n * LEN_IN * CC;
    float acc = 0.f;

    #pragma unroll 4
    for (int p = 0; p < 16; p++) {
        const int l = p >> 2;
        float w  = __shfl_sync(0xffffffffu, prob, p);
        float ox = __shfl_sync(0xffffffffu, offv, 2 * p);
        float oy = __shfl_sync(0xffffffffu, offv, 2 * p + 1);
        float rx = __shfl_sync(0xffffffffu, refv, 2 * l);
        float ry = __shfl_sync(0xffffffffu, refv, 2 * l + 1);

        const int Wi = c_W[l], Hi = c_H[l];
        const float Wf = (float)Wi, Hf = (float)Hi;
        float lx = rx + ox / Wf;
        float ly = ry + oy / Hf;
        float x = lx * Wf - 0.5f;
        float y = ly * Hf - 0.5f;
        float x0f = floorf(x), y0f = floorf(y);
        float wx = x - x0f, wy = y - y0f;
        int x0 = (int)x0f, y0 = (int)y0f;
        const int rowbase = c_start[l];

        #pragma unroll
        for (int cidx = 0; cidx < 4; cidx++) {
            int dx = cidx & 1, dy = cidx >> 1;
            int xi = x0 + dx, yi = y0 + dy;
            float cw = (dx ? wx : 1.f - wx) * (dy ? wy : 1.f - wy);
            if (xi >= 0 && xi < Wi && yi >= 0 && yi < Hi) {
                const float* vp = vbase +
                    (size_t)(rowbase + yi * Wi + xi) * CC + m * 32 + lane;
                acc = fmaf(__ldg(vp), cw * w, acc);
            }
        }
    }

    g_ms[(size_t)nq * 256 + m * 32 + lane] = acc;
}

// ---------------- launch ----------------
extern "C" void kernel_launch(void* const* d_in, const int* in_sizes, int n_in,
                              void* d_out, int out_size)
{
    const float* query         = (const float*)d_in[0];
    const float* refpts        = (const float*)d_in[1];
    const float* input_flatten = (const float*)d_in[2];
    // d_in[3] = input_space_shape, d_in[4] = input_level_start_idx (hardcoded)
    const float* Wv     = (const float*)d_in[5];
    const float* bv     = (const float*)d_in[6];
    const float* W_off  = (const float*)d_in[7];
    const float* b_off  = (const float*)d_in[8];
    const float* W_attn = (const float*)d_in[9];
    const float* b_attn = (const float*)d_in[10];
    const float* Wo     = (const float*)d_in[11];
    const float* bo     = (const float*)d_in[12];
    float* out = (float*)d_out;

    float *p_value, *p_off, *p_attn, *p_ms;
    cudaGetSymbolAddress((void**)&p_value, g_value);
    cudaGetSymbolAddress((void**)&p_off,   g_off);
    cudaGetSymbolAddress((void**)&p_attn,  g_attn);
    cudaGetSymbolAddress((void**)&p_ms,    g_ms);

    dim3 blk(256);
    dim3 g256(256 / BN, (NROWS + BM - 1) / BM);   // (2, 416)
    dim3 g128(128 / BN, (NROWS + BM - 1) / BM);   // (1, 416)

    // 1. value projection
    gemm_tf32_bias<<<g256, blk>>>(input_flatten, Wv, bv, p_value, NROWS, 256);
    // 2. sampling offset logits
    gemm_tf32_bias<<<g256, blk>>>(query, W_off, b_off, p_off, NROWS, 256);
    // 3. attention logits
    gemm_tf32_bias<<<g128, blk>>>(query, W_attn, b_attn, p_attn, NROWS, 128);
    // 4. deformable sampling
    msda_sample<<<NROWS, 256>>>(refpts);
    // 5. output projection
    gemm_tf32_bias<<<g256, blk>>>(p_ms, Wo, bo, out, NROWS, 256);
}

// round 3
// speedup vs baseline: 4.0867x; 1.7218x over previous
#include <cuda_runtime.h>
#include <math.h>
#include <stdint.h>

// ---------------- problem constants (static in reference) ----------------
#define NB 4
#define LQ 13294
#define LEN_IN 13294
#define CC 256
#define NROWS (NB * LQ)   // 53176

__device__ __constant__ int c_H[4]     = {100, 50, 25, 13};
__device__ __constant__ int c_W[4]     = {100, 50, 25, 13};
__device__ __constant__ int c_start[4] = {0, 10000, 12500, 13125};

// ---------------- scratch (device globals, no allocation) ----------------
__device__ float g_value[NROWS * CC];   // (n, len, M*D) value projection
__device__ float g_off[NROWS * CC];     // (n, lq, M*L*P*2) offset logits
__device__ float g_attn[NROWS * 128];   // (n, lq, M*L*P) attn logits
__device__ float g_ms[NROWS * CC];      // (n, lq, C) sampled output

// ---------------- tf32 tensor-core GEMM ----------------
#define BM 128
#define BN 128
#define BK 32
#define ASTRIDE 36
#define BSTRIDE 136

__device__ __forceinline__ uint32_t f2tf32(float x) {
    uint32_t r;
    asm("cvt.rna.tf32.f32 %0, %1;" : "=r"(r) : "f"(x));
    return r;
}

__device__ __forceinline__ void mma_tf32(float* d, const uint32_t* a,
                                         uint32_t b0, uint32_t b1) {
    asm volatile(
        "mma.sync.aligned.m16n8k8.row.col.f32.tf32.tf32.f32 "
        "{%0,%1,%2,%3},{%4,%5,%6,%7},{%8,%9},{%0,%1,%2,%3};"
        : "+f"(d[0]), "+f"(d[1]), "+f"(d[2]), "+f"(d[3])
        : "r"(a[0]), "r"(a[1]), "r"(a[2]), "r"(a[3]), "r"(b0), "r"(b1));
}

__global__ __launch_bounds__(256, 2) void gemm_tf32_bias(
    const float* __restrict__ A, const float* __restrict__ B,
    const float* __restrict__ bias, float* __restrict__ Cmat,
    int Mrows, int Ncols)
{
    __shared__ uint32_t As[BM][ASTRIDE];   // [m][k] tf32
    __shared__ uint32_t Bs[BK][BSTRIDE];   // [k][n] tf32

    const int tid  = threadIdx.x;
    const int lane = tid & 31;
    const int wid  = tid >> 5;
    const int wm   = (wid & 3) * 32;
    const int wn   = (wid >> 2) * 64;
    const int row0 = blockIdx.y * BM;
    const int col0 = blockIdx.x * BN;
    const int K = CC;

    const int r  = lane >> 2;
    const int c  = lane & 3;

    float acc[2][8][4];
    #pragma unroll
    for (int mt = 0; mt < 2; mt++)
        #pragma unroll
        for (int nt = 0; nt < 8; nt++)
            #pragma unroll
            for (int i = 0; i < 4; i++) acc[mt][nt][i] = 0.f;

    for (int k0 = 0; k0 < K; k0 += BK) {
        #pragma unroll
        for (int j = 0; j < 4; j++) {
            int idx = tid + 256 * j;
            int m = idx >> 3;
            int kseg = (idx & 7) << 2;
            int gr = row0 + m;
            float4 v = make_float4(0.f, 0.f, 0.f, 0.f);
            if (gr < Mrows)
                v = *reinterpret_cast<const float4*>(A + (size_t)gr * K + k0 + kseg);
            uint4 u;
            u.x = f2tf32(v.x); u.y = f2tf32(v.y);
            u.z = f2tf32(v.z); u.w = f2tf32(v.w);
            *reinterpret_cast<uint4*>(&As[m][kseg]) = u;
        }
        #pragma unroll
        for (int j = 0; j < 4; j++) {
            int idx = tid + 256 * j;
            int k = idx >> 5;
            int seg = (idx & 31) << 2;
            float4 v = *reinterpret_cast<const float4*>(
                B + (size_t)(k0 + k) * Ncols + col0 + seg);
            uint4 u;
            u.x = f2tf32(v.x); u.y = f2tf32(v.y);
            u.z = f2tf32(v.z); u.w = f2tf32(v.w);
            *reinterpret_cast<uint4*>(&Bs[k][seg]) = u;
        }
        __syncthreads();

        #pragma unroll
        for (int ks = 0; ks < 4; ks++) {
            const int kk = ks * 8;
            uint32_t afr[2][4];
            #pragma unroll
            for (int mt = 0; mt < 2; mt++) {
                int mbase = wm + mt * 16 + r;
                afr[mt][0] = As[mbase][kk + c];
                afr[mt][1] = As[mbase + 8][kk + c];
                afr[mt][2] = As[mbase][kk + c + 4];
                afr[mt][3] = As[mbase + 8][kk + c + 4];
            }
            #pragma unroll
            for (int nt = 0; nt < 8; nt++) {
                int nbase = wn + nt * 8 + r;
                uint32_t b0 = Bs[kk + c][nbase];
                uint32_t b1 = Bs[kk + c + 4][nbase];
                mma_tf32(acc[0][nt], afr[0], b0, b1);
                mma_tf32(acc[1][nt], afr[1], b0, b1);
            }
        }
        __syncthreads();
    }

    const int c2 = c * 2;
    #pragma unroll
    for (int mt = 0; mt < 2; mt++) {
        int row = row0 + wm + mt * 16 + r;
        #pragma unroll
        for (int nt = 0; nt < 8; nt++) {
            int col = col0 + wn + nt * 8 + c2;
            float b0 = __ldg(bias + col);
            float b1 = __ldg(bias + col + 1);
            if (row < Mrows) {
                float2 v = make_float2(acc[mt][nt][0] + b0, acc[mt][nt][1] + b1);
                *reinterpret_cast<float2*>(Cmat + (size_t)row * Ncols + col) = v;
            }
            if (row + 8 < Mrows) {
                float2 v = make_float2(acc[mt][nt][2] + b0, acc[mt][nt][3] + b1);
                *reinterpret_cast<float2*>(Cmat + (size_t)(row + 8) * Ncols + col) = v;
            }
        }
    }
}

// ---------------- sampling: one warp per (n, q, m) ----------------
// Phase 1: lanes 0..15 precompute, for their point, 4 (weight, elem-offset)
//          pairs (OOB corners get weight=0, clamped offset) into smem.
// Phase 2: all 32 lanes run 64 unconditional gather-FMAs (one channel each).
__global__ __launch_bounds__(256) void msda_sample(const float* __restrict__ refpts)
{
    __shared__ float2 s_aw[8][64];      // per warp: 64 (weight, offset) pairs

    const int nq = blockIdx.x;           // n*LQ + q
    const int m = threadIdx.x >> 5;      // head (== warp id in block)
    const int lane = threadIdx.x & 31;
    const int n = nq / LQ;

    if (lane < 16) {
        const int p = lane;
        const int l = p >> 2;

        // softmax over 16 attn logits (width-16 shuffles)
        float logit = g_attn[(size_t)nq * 128 + m * 16 + p];
        float mx = logit;
        #pragma unroll
        for (int o = 8; o >= 1; o >>= 1)
            mx = fmaxf(mx, __shfl_xor_sync(0xffffu, mx, o, 16));
        float e = __expf(logit - mx);
        float s = e;
        #pragma unroll
        for (int o = 8; o >= 1; o >>= 1)
            s += __shfl_xor_sync(0xffffu, s, o, 16);
        float prob = e / s;

        // this point's offset + reference point
        float ox = g_off[(size_t)nq * 256 + m * 32 + 2 * p];
        float oy = g_off[(size_t)nq * 256 + m * 32 + 2 * p + 1];
        float rx = refpts[(size_t)nq * 8 + 2 * l];
        float ry = refpts[(size_t)nq * 8 + 2 * l + 1];

        const int Wi = c_W[l], Hi = c_H[l];
        const float Wf = (float)Wi, Hf = (float)Hi;

        // (rx + ox/W)*W - 0.5 == fma(rx, W, ox) - 0.5
        float x = fmaf(rx, Wf, ox) - 0.5f;
        float y = fmaf(ry, Hf, oy) - 0.5f;
        float x0f = floorf(x), y0f = floorf(y);
        float wx = x - x0f, wy = y - y0f;
        int x0 = (int)x0f, y0 = (int)y0f;
        int x1 = x0 + 1, y1 = y0 + 1;

        float vx0 = (x0 >= 0 && x0 < Wi) ? 1.f : 0.f;
        float vx1 = (x1 >= 0 && x1 < Wi) ? 1.f : 0.f;
        float vy0 = (y0 >= 0 && y0 < Hi) ? 1.f : 0.f;
        float vy1 = (y1 >= 0 && y1 < Hi) ? 1.f : 0.f;

        int cx0 = min(max(x0, 0), Wi - 1);
        int cx1 = min(max(x1, 0), Wi - 1);
        int cy0 = min(max(y0, 0), Hi - 1);
        int cy1 = min(max(y1, 0), Hi - 1);

        const int base = c_start[l];
        int r0 = (base + cy0 * Wi) * CC;
        int r1 = (base + cy1 * Wi) * CC;
        int o00 = r0 + cx0 * CC;
        int o10 = r0 + cx1 * CC;
        int o01 = r1 + cx0 * CC;
        int o11 = r1 + cx1 * CC;

        float wxp = wx * prob;
        float ixp = (1.f - wx) * prob;
        float w00 = ixp * (1.f - wy) * vx0 * vy0;
        float w10 = wxp * (1.f - wy) * vx1 * vy0;
        float w01 = ixp * wy * vx0 * vy1;
        float w11 = wxp * wy * vx1 * vy1;

        s_aw[m][p * 4 + 0] = make_float2(w00, __int_as_float(o00));
        s_aw[m][p * 4 + 1] = make_float2(w10, __int_as_float(o10));
        s_aw[m][p * 4 + 2] = make_float2(w01, __int_as_float(o01));
        s_aw[m][p * 4 + 3] = make_float2(w11, __int_as_float(o11));
    }
    __syncwarp();

    // phase 2: 64 unconditional gather-FMAs per lane (one channel)
    const float* vlane = g_value + (size_t)n * LEN_IN * CC + m * 32 + lane;
    float acc = 0.f;
    #pragma unroll 16
    for (int i = 0; i < 64; i++) {
        float2 e = s_aw[m][i];
        acc = fmaf(__ldg(vlane + __float_as_int(e.y)), e.x, acc);
    }

    g_ms[(size_t)nq * 256 + m * 32 + lane] = acc;
}

// ---------------- launch ----------------
extern "C" void kernel_launch(void* const* d_in, const int* in_sizes, int n_in,
                              void* d_out, int out_size)
{
    const float* query         = (const float*)d_in[0];
    const float* refpts        = (const float*)d_in[1];
    const float* input_flatten = (const float*)d_in[2];
    const float* Wv     = (const float*)d_in[5];
    const float* bv     = (const float*)d_in[6];
    const float* W_off  = (const float*)d_in[7];
    const float* b_off  = (const float*)d_in[8];
    const float* W_attn = (const float*)d_in[9];
    const float* b_attn = (const float*)d_in[10];
    const float* Wo     = (const float*)d_in[11];
    const float* bo     = (const float*)d_in[12];
    float* out = (float*)d_out;

    float *p_value, *p_off, *p_attn, *p_ms;
    cudaGetSymbolAddress((void**)&p_value, g_value);
    cudaGetSymbolAddress((void**)&p_off,   g_off);
    cudaGetSymbolAddress((void**)&p_attn,  g_attn);
    cudaGetSymbolAddress((void**)&p_ms,    g_ms);

    dim3 blk(256);
    dim3 g256(256 / BN, (NROWS + BM - 1) / BM);
    dim3 g128(128 / BN, (NROWS + BM - 1) / BM);

    gemm_tf32_bias<<<g256, blk>>>(input_flatten, Wv, bv, p_value, NROWS, 256);
    gemm_tf32_bias<<<g256, blk>>>(query, W_off, b_off, p_off, NROWS, 256);
    gemm_tf32_bias<<<g128, blk>>>(query, W_attn, b_attn, p_attn, NROWS, 128);
    msda_sample<<<NROWS, 256>>>(refpts);
    gemm_tf32_bias<<<g256, blk>>>(p_ms, Wo, bo, out, NROWS, 256);
}

// round 4
// speedup vs baseline: 4.9783x; 1.2182x over previous
#include <cuda_runtime.h>
#include <math.h>
#include <stdint.h>

// ---------------- problem constants (static in reference) ----------------
#define NB 4
#define LQ 13294
#define LEN_IN 13294
#define CC 256
#define NROWS (NB * LQ)   // 53176

__device__ __constant__ int c_H[4]     = {100, 50, 25, 13};
__device__ __constant__ int c_W[4]     = {100, 50, 25, 13};
__device__ __constant__ int c_start[4] = {0, 10000, 12500, 13125};

// ---------------- scratch (device globals, no allocation) ----------------
__device__ float g_value[NROWS * CC];   // (n, len, M*D) value projection
__device__ float g_off[NROWS * CC];     // (n, lq, M*L*P*2) offset logits
__device__ float g_attn[NROWS * 128];   // (n, lq, M*L*P) attn logits
__device__ float g_ms[NROWS * CC];      // (n, lq, C) sampled output

// ---------------- tf32 tensor-core GEMM ----------------
#define BM 128
#define BN 128
#define BK 32
#define ASTRIDE 36
#define BSTRIDE 136

__device__ __forceinline__ uint32_t f2tf32(float x) {
    uint32_t r;
    asm("cvt.rna.tf32.f32 %0, %1;" : "=r"(r) : "f"(x));
    return r;
}

__device__ __forceinline__ void mma_tf32(float* d, const uint32_t* a,
                                         uint32_t b0, uint32_t b1) {
    asm volatile(
        "mma.sync.aligned.m16n8k8.row.col.f32.tf32.tf32.f32 "
        "{%0,%1,%2,%3},{%4,%5,%6,%7},{%8,%9},{%0,%1,%2,%3};"
        : "+f"(d[0]), "+f"(d[1]), "+f"(d[2]), "+f"(d[3])
        : "r"(a[0]), "r"(a[1]), "r"(a[2]), "r"(a[3]), "r"(b0), "r"(b1));
}

__global__ __launch_bounds__(256, 2) void gemm_tf32_bias(
    const float* __restrict__ A, const float* __restrict__ B,
    const float* __restrict__ bias, float* __restrict__ Cmat,
    int Mrows, int Ncols)
{
    __shared__ uint32_t As[BM][ASTRIDE];   // [m][k] tf32
    __shared__ uint32_t Bs[BK][BSTRIDE];   // [k][n] tf32

    const int tid  = threadIdx.x;
    const int lane = tid & 31;
    const int wid  = tid >> 5;
    const int wm   = (wid & 3) * 32;
    const int wn   = (wid >> 2) * 64;
    const int row0 = blockIdx.y * BM;
    const int col0 = blockIdx.x * BN;
    const int K = CC;

    const int r  = lane >> 2;
    const int c  = lane & 3;

    float acc[2][8][4];
    #pragma unroll
    for (int mt = 0; mt < 2; mt++)
        #pragma unroll
        for (int nt = 0; nt < 8; nt++)
            #pragma unroll
            for (int i = 0; i < 4; i++) acc[mt][nt][i] = 0.f;

    for (int k0 = 0; k0 < K; k0 += BK) {
        #pragma unroll
        for (int j = 0; j < 4; j++) {
            int idx = tid + 256 * j;
            int m = idx >> 3;
            int kseg = (idx & 7) << 2;
            int gr = row0 + m;
            float4 v = make_float4(0.f, 0.f, 0.f, 0.f);
            if (gr < Mrows)
                v = *reinterpret_cast<const float4*>(A + (size_t)gr * K + k0 + kseg);
            uint4 u;
            u.x = f2tf32(v.x); u.y = f2tf32(v.y);
            u.z = f2tf32(v.z); u.w = f2tf32(v.w);
            *reinterpret_cast<uint4*>(&As[m][kseg]) = u;
        }
        #pragma unroll
        for (int j = 0; j < 4; j++) {
            int idx = tid + 256 * j;
            int k = idx >> 5;
            int seg = (idx & 31) << 2;
            float4 v = *reinterpret_cast<const float4*>(
                B + (size_t)(k0 + k) * Ncols + col0 + seg);
            uint4 u;
            u.x = f2tf32(v.x); u.y = f2tf32(v.y);
            u.z = f2tf32(v.z); u.w = f2tf32(v.w);
            *reinterpret_cast<uint4*>(&Bs[k][seg]) = u;
        }
        __syncthreads();

        #pragma unroll
        for (int ks = 0; ks < 4; ks++) {
            const int kk = ks * 8;
            uint32_t afr[2][4];
            #pragma unroll
            for (int mt = 0; mt < 2; mt++) {
                int mbase = wm + mt * 16 + r;
                afr[mt][0] = As[mbase][kk + c];
                afr[mt][1] = As[mbase + 8][kk + c];
                afr[mt][2] = As[mbase][kk + c + 4];
                afr[mt][3] = As[mbase + 8][kk + c + 4];
            }
            #pragma unroll
            for (int nt = 0; nt < 8; nt++) {
                int nbase = wn + nt * 8 + r;
                uint32_t b0 = Bs[kk + c][nbase];
                uint32_t b1 = Bs[kk + c + 4][nbase];
                mma_tf32(acc[0][nt], afr[0], b0, b1);
                mma_tf32(acc[1][nt], afr[1], b0, b1);
            }
        }
        __syncthreads();
    }

    const int c2 = c * 2;
    #pragma unroll
    for (int mt = 0; mt < 2; mt++) {
        int row = row0 + wm + mt * 16 + r;
        #pragma unroll
        for (int nt = 0; nt < 8; nt++) {
            int col = col0 + wn + nt * 8 + c2;
            float b0 = __ldg(bias + col);
            float b1 = __ldg(bias + col + 1);
            if (row < Mrows) {
                float2 v = make_float2(acc[mt][nt][0] + b0, acc[mt][nt][1] + b1);
                *reinterpret_cast<float2*>(Cmat + (size_t)row * Ncols + col) = v;
            }
            if (row + 8 < Mrows) {
                float2 v = make_float2(acc[mt][nt][2] + b0, acc[mt][nt][3] + b1);
                *reinterpret_cast<float2*>(Cmat + (size_t)(row + 8) * Ncols + col) = v;
            }
        }
    }
}

// ---------------- sampling: one warp per (n, q, m) ----------------
// Phase 1 (all 32 lanes): point p = lane&15; half = lane>>4 selects the
//   y0-row (half=0) or y1-row (half=1) corner pair. Each lane emits 2
//   (weight, float4-offset) pairs; OOB corners get weight 0 + clamped index.
// Phase 2: 4 groups of 8 lanes; group g gathers corner i*4+g via LDG.128
//   (4 channels/lane), 16 iterations. Cross-group shuffle reduction, then
//   lanes 0..7 store one float4 each.
__global__ __launch_bounds__(256) void msda_sample(const float* __restrict__ refpts)
{
    __shared__ float2 s_aw[8][64];      // per warp: 64 (weight, f4-offset) pairs

    const int nq = blockIdx.x;           // n*LQ + q
    const int m = threadIdx.x >> 5;      // head (== warp id in block)
    const int lane = threadIdx.x & 31;
    const int n = nq / LQ;

    {
        const int p = lane & 15;
        const int l = p >> 2;
        const int half = lane >> 4;      // dy of this lane's corner pair

        // softmax over 16 attn logits (width-16 shuffles, replicated per half)
        float logit = g_attn[(size_t)nq * 128 + m * 16 + p];
        float mx = logit;
        #pragma unroll
        for (int o = 8; o >= 1; o >>= 1)
            mx = fmaxf(mx, __shfl_xor_sync(0xffffffffu, mx, o, 16));
        float e = __expf(logit - mx);
        float s = e;
        #pragma unroll
        for (int o = 8; o >= 1; o >>= 1)
            s += __shfl_xor_sync(0xffffffffu, s, o, 16);
        float prob = e / s;

        float2 offv = *reinterpret_cast<const float2*>(
            g_off + (size_t)nq * 256 + m * 32 + 2 * p);
        float2 refv = *reinterpret_cast<const float2*>(
            refpts + (size_t)nq * 8 + 2 * l);

        const int Wi = c_W[l], Hi = c_H[l];
        const float Wf = (float)Wi, Hf = (float)Hi;

        // (rx + ox/W)*W - 0.5 == fma(rx, W, ox) - 0.5
        float x = fmaf(refv.x, Wf, offv.x) - 0.5f;
        float y = fmaf(refv.y, Hf, offv.y) - 0.5f;
        float x0f = floorf(x), y0f = floorf(y);
        float wx = x - x0f, wy = y - y0f;
        int x0 = (int)x0f, y0 = (int)y0f;
        int x1 = x0 + 1;
        int yi = y0 + half;

        float vx0 = (x0 >= 0 && x0 < Wi) ? 1.f : 0.f;
        float vx1 = (x1 >= 0 && x1 < Wi) ? 1.f : 0.f;
        float vy  = (yi >= 0 && yi < Hi) ? 1.f : 0.f;
        float wyv = half ? wy : (1.f - wy);

        int cx0 = min(max(x0, 0), Wi - 1);
        int cx1 = min(max(x1, 0), Wi - 1);
        int cyi = min(max(yi, 0), Hi - 1);

        // offsets in float4 units (CC/4 = 64 per value row)
        int rbase = (c_start[l] + cyi * Wi) * 64;
        int o0 = rbase + cx0 * 64;
        int o1 = rbase + cx1 * 64;

        float pv = prob * wyv * vy;
        float w0 = (1.f - wx) * pv * vx0;
        float w1 = wx * pv * vx1;

        float4 st = make_float4(w0, __int_as_float(o0),
                                w1, __int_as_float(o1));
        *reinterpret_cast<float4*>(&s_aw[m][p * 4 + half * 2]) = st;
    }
    __syncwarp();

    // phase 2: grouped float4 gathers
    const int g  = lane >> 3;        // corner group 0..3
    const int lg = lane & 7;         // channel quad within head
    const float4* vbase = reinterpret_cast<const float4*>(
        g_value + (size_t)n * LEN_IN * CC + m * 32) + lg;

    float4 acc = make_float4(0.f, 0.f, 0.f, 0.f);
    #pragma unroll
    for (int i = 0; i < 16; i++) {
        float2 e = s_aw[m][i * 4 + g];
        float4 v = __ldg(vbase + __float_as_int(e.y));
        acc.x = fmaf(v.x, e.x, acc.x);
        acc.y = fmaf(v.y, e.x, acc.y);
        acc.z = fmaf(v.z, e.x, acc.z);
        acc.w = fmaf(v.w, e.x, acc.w);
    }

    // cross-group reduction (groups differ in lane bits 3,4)
    #pragma unroll
    for (int o = 8; o <= 16; o <<= 1) {
        acc.x += __shfl_xor_sync(0xffffffffu, acc.x, o);
        acc.y += __shfl_xor_sync(0xffffffffu, acc.y, o);
        acc.z += __shfl_xor_sync(0xffffffffu, acc.z, o);
        acc.w += __shfl_xor_sync(0xffffffffu, acc.w, o);
    }

    if (lane < 8) {
        *reinterpret_cast<float4*>(
            g_ms + (size_t)nq * 256 + m * 32 + lg * 4) = acc;
    }
}

// ---------------- launch ----------------
extern "C" void kernel_launch(void* const* d_in, const int* in_sizes, int n_in,
                              void* d_out, int out_size)
{
    const float* query         = (const float*)d_in[0];
    const float* refpts        = (const float*)d_in[1];
    const float* input_flatten = (const float*)d_in[2];
    const float* Wv     = (const float*)d_in[5];
    const float* bv     = (const float*)d_in[6];
    const float* W_off  = (const float*)d_in[7];
    const float* b_off  = (const float*)d_in[8];
    const float* W_attn = (const float*)d_in[9];
    const float* b_attn = (const float*)d_in[10];
    const float* Wo     = (const float*)d_in[11];
    const float* bo     = (const float*)d_in[12];
    float* out = (float*)d_out;

    float *p_value, *p_off, *p_attn, *p_ms;
    cudaGetSymbolAddress((void**)&p_value, g_value);
    cudaGetSymbolAddress((void**)&p_off,   g_off);
    cudaGetSymbolAddress((void**)&p_attn,  g_attn);
    cudaGetSymbolAddress((void**)&p_ms,    g_ms);

    dim3 blk(256);
    dim3 g256(256 / BN, (NROWS + BM - 1) / BM);
    dim3 g128(128 / BN, (NROWS + BM - 1) / BM);

    gemm_tf32_bias<<<g256, blk>>>(input_flatten, Wv, bv, p_value, NROWS, 256);
    gemm_tf32_bias<<<g256, blk>>>(query, W_off, b_off, p_off, NROWS, 256);
    gemm_tf32_bias<<<g128, blk>>>(query, W_attn, b_attn, p_attn, NROWS, 128);
    msda_sample<<<NROWS, 256>>>(refpts);
    gemm_tf32_bias<<<g256, blk>>>(p_ms, Wo, bo, out, NROWS, 256);
}

// round 5
// speedup vs baseline: 5.1230x; 1.0291x over previous
#include <cuda_runtime.h>
#include <math.h>
#include <stdint.h>

// ---------------- problem constants (static in reference) ----------------
#define NB 4
#define LQ 13294
#define LEN_IN 13294
#define CC 256
#define NROWS (NB * LQ)   // 53176

__device__ __constant__ int c_H[4]     = {100, 50, 25, 13};
__device__ __constant__ int c_W[4]     = {100, 50, 25, 13};
__device__ __constant__ int c_start[4] = {0, 10000, 12500, 13125};

// ---------------- scratch (device globals, no allocation) ----------------
__device__ float g_value[NROWS * CC];
__device__ float g_off[NROWS * CC];
__device__ float g_attn[NROWS * 128];
__device__ float g_ms[NROWS * CC];

// ---------------- tf32 tensor-core GEMM, register-prefetch pipelined ------
#define BM 128
#define BN 128
#define BK 32
#define ASTRIDE 36
#define BSTRIDE 136

__device__ __forceinline__ uint32_t f2tf32(float x) {
    uint32_t r;
    asm("cvt.rna.tf32.f32 %0, %1;" : "=r"(r) : "f"(x));
    return r;
}

__device__ __forceinline__ void mma_tf32(float* d, const uint32_t* a,
                                         uint32_t b0, uint32_t b1) {
    asm volatile(
        "mma.sync.aligned.m16n8k8.row.col.f32.tf32.tf32.f32 "
        "{%0,%1,%2,%3},{%4,%5,%6,%7},{%8,%9},{%0,%1,%2,%3};"
        : "+f"(d[0]), "+f"(d[1]), "+f"(d[2]), "+f"(d[3])
        : "r"(a[0]), "r"(a[1]), "r"(a[2]), "r"(a[3]), "r"(b0), "r"(b1));
}

__global__ __launch_bounds__(256, 2) void gemm_tf32_bias(
    const float* __restrict__ A, const float* __restrict__ B,
    const float* __restrict__ bias, float* __restrict__ Cmat,
    int Mrows, int Ncols)
{
    __shared__ uint32_t As[BM][ASTRIDE];   // [m][k] tf32
    __shared__ uint32_t Bs[BK][BSTRIDE];   // [k][n] tf32

    const int tid  = threadIdx.x;
    const int lane = tid & 31;
    const int wid  = tid >> 5;
    const int wm   = (wid & 3) * 32;
    const int wn   = (wid >> 2) * 64;
    const int row0 = blockIdx.y * BM;
    const int col0 = blockIdx.x * BN;

    const int r  = lane >> 2;
    const int c  = lane & 3;

    // per-thread load coordinates (4 chunks each for A and B)
    int a_m[4], a_ks[4], b_k[4], b_seg[4];
    bool a_ok[4];
    #pragma unroll
    for (int j = 0; j < 4; j++) {
        int idx = tid + 256 * j;
        a_m[j]  = idx >> 3;
        a_ks[j] = (idx & 7) << 2;
        a_ok[j] = (row0 + a_m[j]) < Mrows;
        b_k[j]  = idx >> 5;
        b_seg[j] = (idx & 31) << 2;
    }

    float acc[2][8][4];
    #pragma unroll
    for (int mt = 0; mt < 2; mt++)
        #pragma unroll
        for (int nt = 0; nt < 8; nt++)
            #pragma unroll
            for (int i = 0; i < 4; i++) acc[mt][nt][i] = 0.f;

    float4 ra[4], rb[4];

    // prologue: load k-tile 0
    #pragma unroll
    for (int j = 0; j < 4; j++) {
        ra[j] = a_ok[j] ? *reinterpret_cast<const float4*>(
                    A + (size_t)(row0 + a_m[j]) * CC + a_ks[j])
                        : make_float4(0.f, 0.f, 0.f, 0.f);
        rb[j] = *reinterpret_cast<const float4*>(
                    B + (size_t)b_k[j] * Ncols + col0 + b_seg[j]);
    }

    #pragma unroll
    for (int kt = 0; kt < CC / BK; kt++) {
        // commit current regs -> smem (tf32 convert)
        #pragma unroll
        for (int j = 0; j < 4; j++) {
            uint4 u;
            u.x = f2tf32(ra[j].x); u.y = f2tf32(ra[j].y);
            u.z = f2tf32(ra[j].z); u.w = f2tf32(ra[j].w);
            *reinterpret_cast<uint4*>(&As[a_m[j]][a_ks[j]]) = u;
            uint4 v;
            v.x = f2tf32(rb[j].x); v.y = f2tf32(rb[j].y);
            v.z = f2tf32(rb[j].z); v.w = f2tf32(rb[j].w);
            *reinterpret_cast<uint4*>(&Bs[b_k[j]][b_seg[j]]) = v;
        }
        __syncthreads();

        // prefetch next k-tile into registers (overlaps with MMA below)
        if (kt < CC / BK - 1) {
            const int k0 = (kt + 1) * BK;
            #pragma unroll
            for (int j = 0; j < 4; j++) {
                ra[j] = a_ok[j] ? *reinterpret_cast<const float4*>(
                            A + (size_t)(row0 + a_m[j]) * CC + k0 + a_ks[j])
                                : make_float4(0.f, 0.f, 0.f, 0.f);
                rb[j] = *reinterpret_cast<const float4*>(
                            B + (size_t)(k0 + b_k[j]) * Ncols + col0 + b_seg[j]);
            }
        }

        #pragma unroll
        for (int ks = 0; ks < 4; ks++) {
            const int kk = ks * 8;
            uint32_t afr[2][4];
            #pragma unroll
            for (int mt = 0; mt < 2; mt++) {
                int mbase = wm + mt * 16 + r;
                afr[mt][0] = As[mbase][kk + c];
                afr[mt][1] = As[mbase + 8][kk + c];
                afr[mt][2] = As[mbase][kk + c + 4];
                afr[mt][3] = As[mbase + 8][kk + c + 4];
            }
            #pragma unroll
            for (int nt = 0; nt < 8; nt++) {
                int nbase = wn + nt * 8 + r;
                uint32_t b0 = Bs[kk + c][nbase];
                uint32_t b1 = Bs[kk + c + 4][nbase];
                mma_tf32(acc[0][nt], afr[0], b0, b1);
                mma_tf32(acc[1][nt], afr[1], b0, b1);
            }
        }
        __syncthreads();
    }

    const int c2 = c * 2;
    #pragma unroll
    for (int mt = 0; mt < 2; mt++) {
        int row = row0 + wm + mt * 16 + r;
        #pragma unroll
        for (int nt = 0; nt < 8; nt++) {
            int col = col0 + wn + nt * 8 + c2;
            float b0 = __ldg(bias + col);
            float b1 = __ldg(bias + col + 1);
            if (row < Mrows) {
                float2 v = make_float2(acc[mt][nt][0] + b0, acc[mt][nt][1] + b1);
                *reinterpret_cast<float2*>(Cmat + (size_t)row * Ncols + col) = v;
            }
            if (row + 8 < Mrows) {
                float2 v = make_float2(acc[mt][nt][2] + b0, acc[mt][nt][3] + b1);
                *reinterpret_cast<float2*>(Cmat + (size_t)(row + 8) * Ncols + col) = v;
            }
        }
    }
}

// ---------------- sampling: one warp per (n, q, m) ----------------
// Phase 1 (all 32 lanes): point p = lane&15, half = lane>>4 (dy). Each lane
//   emits the 2 corners of its row pair into s_aw[m][g][p] with g = dy*2+dx.
// Phase 2: group g (8 lanes) gathers corners from s_aw[m][g][*], two per
//   LDS.128, value rows via LDG.128 (4 channels/lane). Shuffle reduce.
__global__ __launch_bounds__(256) void msda_sample(const float* __restrict__ refpts)
{
    __shared__ float2 s_aw[8][4][16];    // [head][corner-group][point]

    const int nq = blockIdx.x;           // n*LQ + q
    const int m = threadIdx.x >> 5;      // head
    const int lane = threadIdx.x & 31;
    const int n = nq / LQ;

    {
        const int p = lane & 15;
        const int l = p >> 2;
        const int half = lane >> 4;      // dy

        float logit = g_attn[(size_t)nq * 128 + m * 16 + p];
        float mx = logit;
        #pragma unroll
        for (int o = 8; o >= 1; o >>= 1)
            mx = fmaxf(mx, __shfl_xor_sync(0xffffffffu, mx, o, 16));
        float e = __expf(logit - mx);
        float s = e;
        #pragma unroll
        for (int o = 8; o >= 1; o >>= 1)
            s += __shfl_xor_sync(0xffffffffu, s, o, 16);
        float prob = e / s;

        float2 offv = *reinterpret_cast<const float2*>(
            g_off + (size_t)nq * 256 + m * 32 + 2 * p);
        float2 refv = *reinterpret_cast<const float2*>(
            refpts + (size_t)nq * 8 + 2 * l);

        const int Wi = c_W[l], Hi = c_H[l];
        const float Wf = (float)Wi, Hf = (float)Hi;

        float x = fmaf(refv.x, Wf, offv.x) - 0.5f;
        float y = fmaf(refv.y, Hf, offv.y) - 0.5f;
        float x0f = floorf(x), y0f = floorf(y);
        float wx = x - x0f, wy = y - y0f;
        int x0 = (int)x0f, y0 = (int)y0f;
        int x1 = x0 + 1;
        int yi = y0 + half;

        float vx0 = (x0 >= 0 && x0 < Wi) ? 1.f : 0.f;
        float vx1 = (x1 >= 0 && x1 < Wi) ? 1.f : 0.f;
        float vy  = (yi >= 0 && yi < Hi) ? 1.f : 0.f;
        float wyv = half ? wy : (1.f - wy);

        int cx0 = min(max(x0, 0), Wi - 1);
        int cx1 = min(max(x1, 0), Wi - 1);
        int cyi = min(max(yi, 0), Hi - 1);

        int rbase = (c_start[l] + cyi * Wi) * 64;   // float4 units
        int o0 = rbase + cx0 * 64;
        int o1 = rbase + cx1 * 64;

        float pv = prob * wyv * vy;
        float w0 = (1.f - wx) * pv * vx0;
        float w1 = wx * pv * vx1;

        s_aw[m][half * 2 + 0][p] = make_float2(w0, __int_as_float(o0));
        s_aw[m][half * 2 + 1][p] = make_float2(w1, __int_as_float(o1));
    }
    __syncwarp();

    const int g  = lane >> 3;
    const int lg = lane & 7;
    const float4* vbase = reinterpret_cast<const float4*>(
        g_value + (size_t)n * LEN_IN * CC + m * 32) + lg;

    float4 acc = make_float4(0.f, 0.f, 0.f, 0.f);
    #pragma unroll
    for (int i = 0; i < 16; i += 2) {
        float4 e2 = *reinterpret_cast<const float4*>(&s_aw[m][g][i]);
        float4 v0 = __ldg(vbase + __float_as_int(e2.y));
        float4 v1 = __ldg(vbase + __float_as_int(e2.w));
        acc.x = fmaf(v0.x, e2.x, acc.x);
        acc.y = fmaf(v0.y, e2.x, acc.y);
        acc.z = fmaf(v0.z, e2.x, acc.z);
        acc.w = fmaf(v0.w, e2.x, acc.w);
        acc.x = fmaf(v1.x, e2.z, acc.x);
        acc.y = fmaf(v1.y, e2.z, acc.y);
        acc.z = fmaf(v1.z, e2.z, acc.z);
        acc.w = fmaf(v1.w, e2.z, acc.w);
    }

    #pragma unroll
    for (int o = 8; o <= 16; o <<= 1) {
        acc.x += __shfl_xor_sync(0xffffffffu, acc.x, o);
        acc.y += __shfl_xor_sync(0xffffffffu, acc.y, o);
        acc.z += __shfl_xor_sync(0xffffffffu, acc.z, o);
        acc.w += __shfl_xor_sync(0xffffffffu, acc.w, o);
    }

    if (lane < 8) {
        *reinterpret_cast<float4*>(
            g_ms + (size_t)nq * 256 + m * 32 + lg * 4) = acc;
    }
}

// ---------------- launch ----------------
extern "C" void kernel_launch(void* const* d_in, const int* in_sizes, int n_in,
                              void* d_out, int out_size)
{
    const float* query         = (const float*)d_in[0];
    const float* refpts        = (const float*)d_in[1];
    const float* input_flatten = (const float*)d_in[2];
    const float* Wv     = (const float*)d_in[5];
    const float* bv     = (const float*)d_in[6];
    const float* W_off  = (const float*)d_in[7];
    const float* b_off  = (const float*)d_in[8];
    const float* W_attn = (const float*)d_in[9];
    const float* b_attn = (const float*)d_in[10];
    const float* Wo     = (const float*)d_in[11];
    const float* bo     = (const float*)d_in[12];
    float* out = (float*)d_out;

    float *p_value, *p_off, *p_attn, *p_ms;
    cudaGetSymbolAddress((void**)&p_value, g_value);
    cudaGetSymbolAddress((void**)&p_off,   g_off);
    cudaGetSymbolAddress((void**)&p_attn,  g_attn);
    cudaGetSymbolAddress((void**)&p_ms,    g_ms);

    dim3 blk(256);
    dim3 g256(256 / BN, (NROWS + BM - 1) / BM);
    dim3 g128(128 / BN, (NROWS + BM - 1) / BM);

    gemm_tf32_bias<<<g256, blk>>>(input_flatten, Wv, bv, p_value, NROWS, 256);
    gemm_tf32_bias<<<g256, blk>>>(query, W_off, b_off, p_off, NROWS, 256);
    gemm_tf32_bias<<<g128, blk>>>(query, W_attn, b_attn, p_attn, NROWS, 128);
    msda_sample<<<NROWS, 256>>>(refpts);
    gemm_tf32_bias<<<g256, blk>>>(p_ms, Wo, bo, out, NROWS, 256);
}

// round 6
// speedup vs baseline: 5.3038x; 1.0353x over previous
#include <cuda_runtime.h>
#include <math.h>
#include <stdint.h>

// ---------------- problem constants (static in reference) ----------------
#define NB 4
#define LQ 13294
#define LEN_IN 13294
#define CC 256
#define NROWS (NB * LQ)   // 53176
#define NFUSE 384         // 256 offset logits + 128 attn logits

__device__ __constant__ int c_H[4]     = {100, 50, 25, 13};
__device__ __constant__ int c_W[4]     = {100, 50, 25, 13};
__device__ __constant__ int c_start[4] = {0, 10000, 12500, 13125};

// ---------------- scratch (device globals, no allocation) ----------------
__device__ float g_value[NROWS * CC];     // value projection
__device__ float g_oa[NROWS * NFUSE];     // fused [off(256) | attn(128)] logits
__device__ float g_ms[NROWS * CC];        // sampled output
__device__ float g_Wf[CC * NFUSE];        // concatenated [W_off | W_attn]
__device__ float g_bf[NFUSE];             // concatenated [b_off | b_attn]

// ---------------- prep: concat weights/biases ----------------
__global__ void concat_wb(const float* __restrict__ W_off,
                          const float* __restrict__ W_attn,
                          const float* __restrict__ b_off,
                          const float* __restrict__ b_attn,
                          float* __restrict__ Wf, float* __restrict__ bf)
{
    int i = blockIdx.x * 256 + threadIdx.x;
    if (i < CC * NFUSE) {
        int k = i / NFUSE, c = i % NFUSE;
        Wf[i] = (c < 256) ? W_off[k * 256 + c] : W_attn[k * 128 + (c - 256)];
    }
    if (i < NFUSE) bf[i] = (i < 256) ? b_off[i] : b_attn[i - 256];
}

// ---------------- tf32 tensor-core GEMM, register-prefetch pipelined ------
#define BM 128
#define BN 128
#define BK 32
#define ASTRIDE 36
#define BSTRIDE 136

__device__ __forceinline__ uint32_t f2tf32(float x) {
    uint32_t r;
    asm("cvt.rna.tf32.f32 %0, %1;" : "=r"(r) : "f"(x));
    return r;
}

__device__ __forceinline__ void mma_tf32(float* d, const uint32_t* a,
                                         uint32_t b0, uint32_t b1) {
    asm volatile(
        "mma.sync.aligned.m16n8k8.row.col.f32.tf32.tf32.f32 "
        "{%0,%1,%2,%3},{%4,%5,%6,%7},{%8,%9},{%0,%1,%2,%3};"
        : "+f"(d[0]), "+f"(d[1]), "+f"(d[2]), "+f"(d[3])
        : "r"(a[0]), "r"(a[1]), "r"(a[2]), "r"(a[3]), "r"(b0), "r"(b1));
}

__global__ __launch_bounds__(256, 2) void gemm_tf32_bias(
    const float* __restrict__ A, const float* __restrict__ B,
    const float* __restrict__ bias, float* __restrict__ Cmat,
    int Mrows, int Ncols)
{
    __shared__ uint32_t As[BM][ASTRIDE];   // [m][k] tf32
    __shared__ uint32_t Bs[BK][BSTRIDE];   // [k][n] tf32

    const int tid  = threadIdx.x;
    const int lane = tid & 31;
    const int wid  = tid >> 5;
    const int wm   = (wid & 3) * 32;
    const int wn   = (wid >> 2) * 64;
    const int row0 = blockIdx.y * BM;
    const int col0 = blockIdx.x * BN;

    const int r  = lane >> 2;
    const int c  = lane & 3;

    int a_m[4], a_ks[4], b_k[4], b_seg[4];
    bool a_ok[4];
    #pragma unroll
    for (int j = 0; j < 4; j++) {
        int idx = tid + 256 * j;
        a_m[j]  = idx >> 3;
        a_ks[j] = (idx & 7) << 2;
        a_ok[j] = (row0 + a_m[j]) < Mrows;
        b_k[j]  = idx >> 5;
        b_seg[j] = (idx & 31) << 2;
    }

    float acc[2][8][4];
    #pragma unroll
    for (int mt = 0; mt < 2; mt++)
        #pragma unroll
        for (int nt = 0; nt < 8; nt++)
            #pragma unroll
            for (int i = 0; i < 4; i++) acc[mt][nt][i] = 0.f;

    float4 ra[4], rb[4];

    #pragma unroll
    for (int j = 0; j < 4; j++) {
        ra[j] = a_ok[j] ? *reinterpret_cast<const float4*>(
                    A + (size_t)(row0 + a_m[j]) * CC + a_ks[j])
                        : make_float4(0.f, 0.f, 0.f, 0.f);
        rb[j] = *reinterpret_cast<const float4*>(
                    B + (size_t)b_k[j] * Ncols + col0 + b_seg[j]);
    }

    #pragma unroll
    for (int kt = 0; kt < CC / BK; kt++) {
        #pragma unroll
        for (int j = 0; j < 4; j++) {
            uint4 u;
            u.x = f2tf32(ra[j].x); u.y = f2tf32(ra[j].y);
            u.z = f2tf32(ra[j].z); u.w = f2tf32(ra[j].w);
            *reinterpret_cast<uint4*>(&As[a_m[j]][a_ks[j]]) = u;
            uint4 v;
            v.x = f2tf32(rb[j].x); v.y = f2tf32(rb[j].y);
            v.z = f2tf32(rb[j].z); v.w = f2tf32(rb[j].w);
            *reinterpret_cast<uint4*>(&Bs[b_k[j]][b_seg[j]]) = v;
        }
        __syncthreads();

        if (kt < CC / BK - 1) {
            const int k0 = (kt + 1) * BK;
            #pragma unroll
            for (int j = 0; j < 4; j++) {
                ra[j] = a_ok[j] ? *reinterpret_cast<const float4*>(
                            A + (size_t)(row0 + a_m[j]) * CC + k0 + a_ks[j])
                                : make_float4(0.f, 0.f, 0.f, 0.f);
                rb[j] = *reinterpret_cast<const float4*>(
                            B + (size_t)(k0 + b_k[j]) * Ncols + col0 + b_seg[j]);
            }
        }

        #pragma unroll
        for (int ks = 0; ks < 4; ks++) {
            const int kk = ks * 8;
            uint32_t afr[2][4];
            #pragma unroll
            for (int mt = 0; mt < 2; mt++) {
                int mbase = wm + mt * 16 + r;
                afr[mt][0] = As[mbase][kk + c];
                afr[mt][1] = As[mbase + 8][kk + c];
                afr[mt][2] = As[mbase][kk + c + 4];
                afr[mt][3] = As[mbase + 8][kk + c + 4];
            }
            #pragma unroll
            for (int nt = 0; nt < 8; nt++) {
                int nbase = wn + nt * 8 + r;
                uint32_t b0 = Bs[kk + c][nbase];
                uint32_t b1 = Bs[kk + c + 4][nbase];
                mma_tf32(acc[0][nt], afr[0], b0, b1);
                mma_tf32(acc[1][nt], afr[1], b0, b1);
            }
        }
        __syncthreads();
    }

    const int c2 = c * 2;
    #pragma unroll
    for (int mt = 0; mt < 2; mt++) {
        int row = row0 + wm + mt * 16 + r;
        #pragma unroll
        for (int nt = 0; nt < 8; nt++) {
            int col = col0 + wn + nt * 8 + c2;
            float b0 = __ldg(bias + col);
            float b1 = __ldg(bias + col + 1);
            if (row < Mrows) {
                float2 v = make_float2(acc[mt][nt][0] + b0, acc[mt][nt][1] + b1);
                *reinterpret_cast<float2*>(Cmat + (size_t)row * Ncols + col) = v;
            }
            if (row + 8 < Mrows) {
                float2 v = make_float2(acc[mt][nt][2] + b0, acc[mt][nt][3] + b1);
                *reinterpret_cast<float2*>(Cmat + (size_t)(row + 8) * Ncols + col) = v;
            }
        }
    }
}

// ---------------- sampling: one warp per (n, q, m) ----------------
// Phase 1 (all 32 lanes): point p = lane&15; half = lane>>4 picks the y-row.
//   Each lane emits 2 (weight, float4-offset) pairs into the interleaved
//   conflict-free layout s_aw[m][p*4 + corner].
// Phase 2: 4 groups of 8 lanes; group g gathers corner i*4+g via LDG.128
//   (4 channels/lane). Cross-group shuffle reduction, lanes 0..7 store.
__global__ __launch_bounds__(256) void msda_sample(const float* __restrict__ refpts)
{
    __shared__ float2 s_aw[8][64];      // per warp: 64 (weight, f4-offset) pairs

    const int nq = blockIdx.x;           // n*LQ + q
    const int m = threadIdx.x >> 5;      // head
    const int lane = threadIdx.x & 31;
    const int n = nq / LQ;

    {
        const int p = lane & 15;
        const int l = p >> 2;
        const int half = lane >> 4;      // dy

        float logit = g_oa[(size_t)nq * NFUSE + 256 + m * 16 + p];
        float mx = logit;
        #pragma unroll
        for (int o = 8; o >= 1; o >>= 1)
            mx = fmaxf(mx, __shfl_xor_sync(0xffffffffu, mx, o, 16));
        float e = __expf(logit - mx);
        float s = e;
        #pragma unroll
        for (int o = 8; o >= 1; o >>= 1)
            s += __shfl_xor_sync(0xffffffffu, s, o, 16);
        float prob = e / s;

        float2 offv = *reinterpret_cast<const float2*>(
            g_oa + (size_t)nq * NFUSE + m * 32 + 2 * p);
        float2 refv = *reinterpret_cast<const float2*>(
            refpts + (size_t)nq * 8 + 2 * l);

        const int Wi = c_W[l], Hi = c_H[l];
        const float Wf = (float)Wi, Hf = (float)Hi;

        float x = fmaf(refv.x, Wf, offv.x) - 0.5f;
        float y = fmaf(refv.y, Hf, offv.y) - 0.5f;
        float x0f = floorf(x), y0f = floorf(y);
        float wx = x - x0f, wy = y - y0f;
        int x0 = (int)x0f, y0 = (int)y0f;
        int x1 = x0 + 1;
        int yi = y0 + half;

        float vx0 = (x0 >= 0 && x0 < Wi) ? 1.f : 0.f;
        float vx1 = (x1 >= 0 && x1 < Wi) ? 1.f : 0.f;
        float vy  = (yi >= 0 && yi < Hi) ? 1.f : 0.f;
        float wyv = half ? wy : (1.f - wy);

        int cx0 = min(max(x0, 0), Wi - 1);
        int cx1 = min(max(x1, 0), Wi - 1);
        int cyi = min(max(yi, 0), Hi - 1);

        int rbase = (c_start[l] + cyi * Wi) * 64;   // float4 units
        int o0 = rbase + cx0 * 64;
        int o1 = rbase + cx1 * 64;

        float pv = prob * wyv * vy;
        float w0 = (1.f - wx) * pv * vx0;
        float w1 = wx * pv * vx1;

        float4 st = make_float4(w0, __int_as_float(o0),
                                w1, __int_as_float(o1));
        *reinterpret_cast<float4*>(&s_aw[m][p * 4 + half * 2]) = st;
    }
    __syncwarp();

    const int g  = lane >> 3;
    const int lg = lane & 7;
    const float4* vbase = reinterpret_cast<const float4*>(
        g_value + (size_t)n * LEN_IN * CC + m * 32) + lg;

    float4 acc = make_float4(0.f, 0.f, 0.f, 0.f);
    #pragma unroll
    for (int i = 0; i < 16; i++) {
        float2 e = s_aw[m][i * 4 + g];
        float4 v = __ldg(vbase + __float_as_int(e.y));
        acc.x = fmaf(v.x, e.x, acc.x);
        acc.y = fmaf(v.y, e.x, acc.y);
        acc.z = fmaf(v.z, e.x, acc.z);
        acc.w = fmaf(v.w, e.x, acc.w);
    }

    #pragma unroll
    for (int o = 8; o <= 16; o <<= 1) {
        acc.x += __shfl_xor_sync(0xffffffffu, acc.x, o);
        acc.y += __shfl_xor_sync(0xffffffffu, acc.y, o);
        acc.z += __shfl_xor_sync(0xffffffffu, acc.z, o);
        acc.w += __shfl_xor_sync(0xffffffffu, acc.w, o);
    }

    if (lane < 8) {
        *reinterpret_cast<float4*>(
            g_ms + (size_t)nq * 256 + m * 32 + lg * 4) = acc;
    }
}

// ---------------- launch ----------------
extern "C" void kernel_launch(void* const* d_in, const int* in_sizes, int n_in,
                              void* d_out, int out_size)
{
    const float* query         = (const float*)d_in[0];
    const float* refpts        = (const float*)d_in[1];
    const float* input_flatten = (const float*)d_in[2];
    const float* Wv     = (const float*)d_in[5];
    const float* bv     = (const float*)d_in[6];
    const float* W_off  = (const float*)d_in[7];
    const float* b_off  = (const float*)d_in[8];
    const float* W_attn = (const float*)d_in[9];
    const float* b_attn = (const float*)d_in[10];
    const float* Wo     = (const float*)d_in[11];
    const float* bo     = (const float*)d_in[12];
    float* out = (float*)d_out;

    float *p_value, *p_oa, *p_ms, *p_Wf, *p_bf;
    cudaGetSymbolAddress((void**)&p_value, g_value);
    cudaGetSymbolAddress((void**)&p_oa,    g_oa);
    cudaGetSymbolAddress((void**)&p_ms,    g_ms);
    cudaGetSymbolAddress((void**)&p_Wf,    g_Wf);
    cudaGetSymbolAddress((void**)&p_bf,    g_bf);

    dim3 blk(256);
    dim3 g256(256 / BN, (NROWS + BM - 1) / BM);   // (2, 416)
    dim3 g384(NFUSE / BN, (NROWS + BM - 1) / BM); // (3, 416)

    // 0. concat [W_off | W_attn] and biases
    concat_wb<<<(CC * NFUSE + 255) / 256, 256>>>(W_off, W_attn, b_off, b_attn,
                                                 p_Wf, p_bf);
    // 1. value projection
    gemm_tf32_bias<<<g256, blk>>>(input_flatten, Wv, bv, p_value, NROWS, 256);
    // 2+3. fused offsets + attn logits
    gemm_tf32_bias<<<g384, blk>>>(query, p_Wf, p_bf, p_oa, NROWS, NFUSE);
    // 4. deformable sampling
    msda_sample<<<NROWS, 256>>>(refpts);
    // 5. output projection
    gemm_tf32_bias<<<g256, blk>>>(p_ms, Wo, bo, out, NROWS, 256);
}